// round 14
// baseline (speedup 1.0000x reference)
#include <cuda_runtime.h>
#include <cuda_bf16.h>
#include <math.h>
#include <stdint.h>

#define NN   50000
#define EE   800000
#define MM   3
#define INSZ 256
#define HDIM 128
#define NH   8
#define DH   16
#define OUTC 8
#define SAH  128
#define ZROW (MM*HDIM)
#define SAROWS (NN*MM)
#define FSTR 36
#define FEAT_DYN (4*128*FSTR*4)

__device__ __align__(16) __nv_bfloat16 g_feat16[(size_t)MM*NN*HDIM];
__device__ __align__(16) float g_z[(size_t)SAROWS*HDIM];
__device__ float g_el[MM*NN*NH];
__device__ float g_er[MM*NN*NH];
__device__ int   g_deg[MM*NN];
__device__ int   g_off[MM*(NN+1)];
__device__ int   g_cur[MM*NN];
__device__ int   g_srt[MM*EE];
__device__ float g_w[SAROWS];
__device__ float g_den[MM];
__device__ float g_fus[MM*HDIM];
__device__ __align__(16) float g_wt[MM*HDIM*INSZ];
__device__ __align__(16) float g_w1t[SAH*HDIM];

__device__ __forceinline__ uint32_t smem_u32(const void* p) {
    uint32_t a;
    asm("{ .reg .u64 t; cvta.to.shared.u64 t, %1; cvt.u32.u64 %0, t; }" : "=r"(a) : "l"(p));
    return a;
}
__device__ __forceinline__ void cp_async16(uint32_t saddr, const void* g) {
    asm volatile("cp.async.cg.shared.global [%0], [%1], 16;" :: "r"(saddr), "l"(g));
}
__device__ __forceinline__ void cp_async16z(uint32_t saddr, const void* g, int sz) {
    asm volatile("cp.async.cg.shared.global [%0], [%1], 16, %2;" :: "r"(saddr), "l"(g), "r"(sz));
}
#define CP_COMMIT() asm volatile("cp.async.commit_group;" ::: "memory")
#define CP_WAIT0()  asm volatile("cp.async.wait_group 0;" ::: "memory")
#define CP_WAIT1()  asm volatile("cp.async.wait_group 1;" ::: "memory")
__device__ __forceinline__ uint32_t tf32r_u(float x) {
    uint32_t u;
    asm("cvt.rna.tf32.f32 %0, %1;" : "=r"(u) : "f"(x));
    return u;
}
__device__ __forceinline__ void mma_tf32(float* c, const uint32_t* a, uint32_t b0, uint32_t b1) {
    asm volatile("mma.sync.aligned.m16n8k8.row.col.f32.tf32.tf32.f32 "
        "{%0,%1,%2,%3}, {%4,%5,%6,%7}, {%8,%9}, {%0,%1,%2,%3};"
        : "+f"(c[0]), "+f"(c[1]), "+f"(c[2]), "+f"(c[3])
        : "r"(a[0]), "r"(a[1]), "r"(a[2]), "r"(a[3]), "r"(b0), "r"(b1));
}

__global__ void k_init() {
    int idx = blockIdx.x * blockDim.x + threadIdx.x;
    if (idx < MM*NN) g_deg[idx] = 0;
}

__global__ void k_prep(const float* __restrict__ fc_w, const float* __restrict__ sa_w1) {
    int idx = blockIdx.x * blockDim.x + threadIdx.x;
    if (idx < MM*HDIM*INSZ) {
        int m = idx / (HDIM*INSZ), r = idx - m*(HDIM*INSZ);
        int n = r / INSZ, k = r - n*INSZ;
        g_wt[idx] = __uint_as_float(tf32r_u(fc_w[((size_t)m*INSZ + k)*HDIM + n]));
    } else {
        int j = idx - MM*HDIM*INSZ;
        if (j < SAH*HDIM) {
            int n = j / HDIM, k = j - n*HDIM;
            g_w1t[j] = __uint_as_float(tf32r_u(sa_w1[(size_t)k*SAH + n]));
        } else {
            int q = j - SAH*HDIM;
            if (q < MM*HDIM) g_fus[q] = 0.f;
            else if (q < MM*HDIM + MM) g_den[q - MM*HDIM] = 0.f;
        }
    }
}

// ---- feat = h @ fc_w[m], tf32 mma, double-buffered cp.async pipeline ----
__global__ __launch_bounds__(256, 2) void k_feat_mma(const float* __restrict__ A,
                                                     const float* __restrict__ AL,
                                                     const float* __restrict__ AR) {
    extern __shared__ __align__(16) float smf[];
    float* sA = smf;
    float* sB = smf + 2*128*FSTR;
    __shared__ float s_al[128], s_ar[128];
    int tid = threadIdx.x, w = tid >> 5, lane = tid & 31;
    int wm = w >> 1, wn = w & 1, g = lane >> 2, t4 = lane & 3;
    int m = blockIdx.y, row0 = blockIdx.x * 128;
    if (tid < 128) { s_al[tid] = AL[m*HDIM + tid]; s_ar[tid] = AR[m*HDIM + tid]; }
    float acc[2][8][4];
#pragma unroll
    for (int mt = 0; mt < 2; mt++)
#pragma unroll
        for (int j = 0; j < 8; j++)
#pragma unroll
            for (int i = 0; i < 4; i++) acc[mt][j][i] = 0.f;

    const float* Bm = g_wt + (size_t)m * HDIM * INSZ;
    int r_ld = tid >> 3, q_ld = tid & 7;

    auto stage = [&](int kc, int buf) {
        int k0 = kc * 32;
        uint32_t aA = smem_u32(sA + buf*128*FSTR);
        uint32_t aB = smem_u32(sB + buf*128*FSTR);
#pragma unroll
        for (int i = 0; i < 4; i++) {
            int r = r_ld + i*32, q = q_ld;
            int node = row0 + r;
            const float* src = A + (size_t)(node < NN ? node : 0) * INSZ + k0 + q * 4;
            cp_async16z(aA + (uint32_t)(r*FSTR + q*4)*4, src, node < NN ? 16 : 0);
            cp_async16(aB + (uint32_t)(r*FSTR + q*4)*4, Bm + (size_t)r * INSZ + k0 + q * 4);
        }
        CP_COMMIT();
    };

    stage(0, 0);
    for (int kc = 0; kc < 8; kc++) {
        if (kc < 7) { stage(kc + 1, (kc + 1) & 1); CP_WAIT1(); }
        else        { CP_WAIT0(); }
        __syncthreads();
        const float* sAb = sA + (kc & 1)*128*FSTR;
        const float* sBb = sB + (kc & 1)*128*FSTR;
#pragma unroll
        for (int ks = 0; ks < 4; ks++) {
            int kb = ks * 8;
            uint32_t af[2][4];
#pragma unroll
            for (int mt = 0; mt < 2; mt++) {
                int ar_ = wm*32 + mt*16 + g;
                af[mt][0] = tf32r_u(sAb[ar_*FSTR + kb + t4]);
                af[mt][1] = tf32r_u(sAb[(ar_+8)*FSTR + kb + t4]);
                af[mt][2] = tf32r_u(sAb[ar_*FSTR + kb + t4 + 4]);
                af[mt][3] = tf32r_u(sAb[(ar_+8)*FSTR + kb + t4 + 4]);
            }
#pragma unroll
            for (int jp = 0; jp < 8; jp++) {
                int bn = wn*64 + jp*8 + g;
                uint32_t b0 = __float_as_uint(sBb[bn*FSTR + kb + t4]);
                uint32_t b1 = __float_as_uint(sBb[bn*FSTR + kb + t4 + 4]);
                mma_tf32(acc[0][jp], af[0], b0, b1);
                mma_tf32(acc[1][jp], af[1], b0, b1);
            }
        }
        __syncthreads();
    }
    __nv_bfloat16* outp = g_feat16 + (size_t)m * NN * HDIM;
#pragma unroll
    for (int mt = 0; mt < 2; mt++) {
        int r0 = row0 + wm*32 + mt*16 + g;
#pragma unroll
        for (int jp = 0; jp < 8; jp++) {
            int col = wn*64 + jp*8 + t4*2;
            if (r0 < NN)
                *(__nv_bfloat162*)(outp + (size_t)r0 * HDIM + col) =
                    __float22bfloat162_rn(make_float2(acc[mt][jp][0], acc[mt][jp][1]));
            if (r0 + 8 < NN)
                *(__nv_bfloat162*)(outp + (size_t)(r0 + 8) * HDIM + col) =
                    __float22bfloat162_rn(make_float2(acc[mt][jp][2], acc[mt][jp][3]));
        }
#pragma unroll
        for (int hh = 0; hh < 4; hh++) {
            float pl0 = 0.f, pr0 = 0.f, pl1 = 0.f, pr1 = 0.f;
#pragma unroll
            for (int jj = 2*hh; jj <= 2*hh+1; jj++) {
                int c0 = wn*64 + jj*8 + t4*2, c1 = c0 + 1;
                float a0 = s_al[c0], a1 = s_al[c1], b0 = s_ar[c0], b1 = s_ar[c1];
                pl0 += acc[mt][jj][0]*a0 + acc[mt][jj][1]*a1;
                pr0 += acc[mt][jj][0]*b0 + acc[mt][jj][1]*b1;
                pl1 += acc[mt][jj][2]*a0 + acc[mt][jj][3]*a1;
                pr1 += acc[mt][jj][2]*b0 + acc[mt][jj][3]*b1;
            }
            pl0 += __shfl_xor_sync(0xffffffffu, pl0, 1); pl0 += __shfl_xor_sync(0xffffffffu, pl0, 2);
            pr0 += __shfl_xor_sync(0xffffffffu, pr0, 1); pr0 += __shfl_xor_sync(0xffffffffu, pr0, 2);
            pl1 += __shfl_xor_sync(0xffffffffu, pl1, 1); pl1 += __shfl_xor_sync(0xffffffffu, pl1, 2);
            pr1 += __shfl_xor_sync(0xffffffffu, pr1, 1); pr1 += __shfl_xor_sync(0xffffffffu, pr1, 2);
            if (t4 == 0) {
                int h = wn*4 + hh;
                if (r0 < NN) {
                    g_el[(m*NN + r0)*NH + h] = pl0;
                    g_er[(m*NN + r0)*NH + h] = pr0;
                }
                if (r0 + 8 < NN) {
                    g_el[(m*NN + r0 + 8)*NH + h] = pl1;
                    g_er[(m*NN + r0 + 8)*NH + h] = pr1;
                }
            }
        }
    }
}

// ---- SA GEMM tf32 + fused tanh epilogue (no wmax — softmax shift-free) ----
__global__ __launch_bounds__(256, 2) void k_sa_mma(const float* __restrict__ B1,
                                                   const float* __restrict__ W2) {
    __shared__ __align__(16) float sA[128*FSTR], sB[128*FSTR];
    __shared__ float s_b1[128], s_w2[128];
    int tid = threadIdx.x, w = tid >> 5, lane = tid & 31;
    int g = lane >> 2, t4 = lane & 3;
    int row0 = blockIdx.x * 128;
    if (tid < 128) { s_b1[tid] = B1[tid]; s_w2[tid] = W2[tid]; }
    uint32_t aA = smem_u32(sA), aB = smem_u32(sB);
    float acc[16][4];
#pragma unroll
    for (int j = 0; j < 16; j++)
#pragma unroll
        for (int i = 0; i < 4; i++) acc[j][i] = 0.f;

    for (int kc = 0; kc < 4; kc++) {
        int k0 = kc * 32;
#pragma unroll
        for (int i = 0; i < 4; i++) {
            int p = i * 256 + tid;
            int r = p >> 3, q = p & 7;
            int row = row0 + r;
            const float* src = g_z + (size_t)(row < SAROWS ? row : 0) * HDIM + k0 + q * 4;
            cp_async16z(aA + (uint32_t)(r*FSTR + q*4)*4, src, row < SAROWS ? 16 : 0);
            cp_async16(aB + (uint32_t)(r*FSTR + q*4)*4, g_w1t + (size_t)r * HDIM + k0 + q * 4);
        }
        CP_COMMIT();
        CP_WAIT0();
        __syncthreads();
#pragma unroll
        for (int ks = 0; ks < 4; ks++) {
            int kb = ks * 8;
            int ar_ = w*16 + g;
            uint32_t af[4];
            af[0] = tf32r_u(sA[ar_*FSTR + kb + t4]);
            af[1] = tf32r_u(sA[(ar_+8)*FSTR + kb + t4]);
            af[2] = tf32r_u(sA[ar_*FSTR + kb + t4 + 4]);
            af[3] = tf32r_u(sA[(ar_+8)*FSTR + kb + t4 + 4]);
#pragma unroll
            for (int jp = 0; jp < 16; jp++) {
                int bn = jp*8 + g;
                uint32_t b0 = __float_as_uint(sB[bn*FSTR + kb + t4]);
                uint32_t b1 = __float_as_uint(sB[bn*FSTR + kb + t4 + 4]);
                mma_tf32(acc[jp], af, b0, b1);
            }
        }
        __syncthreads();
    }
    float s0 = 0.f, s1 = 0.f;
#pragma unroll
    for (int j = 0; j < 16; j++) {
        int col = j * 8 + t4 * 2;
        float b0 = s_b1[col], b1v = s_b1[col + 1];
        float w0 = s_w2[col], w1v = s_w2[col + 1];
        s0 += tanhf(acc[j][0] + b0) * w0 + tanhf(acc[j][1] + b1v) * w1v;
        s1 += tanhf(acc[j][2] + b0) * w0 + tanhf(acc[j][3] + b1v) * w1v;
    }
    s0 += __shfl_xor_sync(0xffffffffu, s0, 1); s0 += __shfl_xor_sync(0xffffffffu, s0, 2);
    s1 += __shfl_xor_sync(0xffffffffu, s1, 1); s1 += __shfl_xor_sync(0xffffffffu, s1, 2);
    if (t4 == 0) {
        int r0 = row0 + w * 16 + g;
        if (r0 < SAROWS)     g_w[r0]     = s0;
        if (r0 + 8 < SAROWS) g_w[r0 + 8] = s1;
    }
}

// ---- CSR build: scalar 1 edge/thread ----
__global__ void k_hist(const int* __restrict__ edges) {
    int idx = blockIdx.x * blockDim.x + threadIdx.x;
    if (idx >= MM*EE) return;
    int m = idx / EE, e = idx - m*EE;
    atomicAdd(&g_deg[m*NN + edges[(size_t)m*2*EE + EE + e]], 1);
}

__global__ void k_scan() {
    __shared__ int sh[1024];
    int m = blockIdx.x, t = threadIdx.x;
    const int CH = (NN + 1023) / 1024;
    int base = t * CH, sum = 0;
    for (int i = 0; i < CH; i++) { int idx = base+i; if (idx < NN) sum += g_deg[m*NN+idx]; }
    sh[t] = sum; __syncthreads();
    for (int d = 1; d < 1024; d <<= 1) {
        int v = (t >= d) ? sh[t-d] : 0; __syncthreads();
        sh[t] += v; __syncthreads();
    }
    int run = sh[t] - sum;
    for (int i = 0; i < CH; i++) {
        int idx = base+i;
        if (idx < NN) { g_off[m*(NN+1)+idx] = run; g_cur[m*NN+idx] = run; run += g_deg[m*NN+idx]; }
    }
    if (t == 1023) g_off[m*(NN+1)+NN] = sh[1023];
}

__global__ void k_scatter(const int* __restrict__ edges) {
    int idx = blockIdx.x * blockDim.x + threadIdx.x;
    if (idx >= MM*EE) return;
    int m = idx / EE, e = idx - m*EE;
    int src = edges[(size_t)m*2*EE + e];
    int dst = edges[(size_t)m*2*EE + EE + e];
    g_srt[(size_t)m*EE + atomicAdd(&g_cur[m*NN + dst], 1)] = src;
}

// ---- GAT aggregation: 2 warps per node (dim-split 64/64), unroll-8 ----
__global__ __launch_bounds__(256) void k_agg() {
    int lane = threadIdx.x & 31;
    int gwid = (blockIdx.x * blockDim.x + threadIdx.x) >> 5;
    int m    = blockIdx.y;
    int n = gwid >> 1, split = gwid & 1;
    if (n >= NN) return;
    int h = split*4 + (lane >> 3);        // this lane's head
    int dimo = split*64 + lane*2;         // this lane's 2 dims
    int beg = g_off[m*(NN+1)+n], end = g_off[m*(NN+1)+n+1];
    float ern = g_er[(m*NN+n)*NH + h];
    const __nv_bfloat16* featm = g_feat16 + (size_t)m*HDIM*NN;
    const float* elm = g_el + m*NN*NH;
    const int*   srcs = g_srt + (size_t)m*EE;
    float den = 0.f, ax = 0.f, ay = 0.f;
    float dn2 = 0.f, bx = 0.f, by = 0.f;
    int i = beg;
    for (; i + 8 <= end; i += 8) {
        int s[8]; float e[8]; uint32_t f[8];
#pragma unroll
        for (int j = 0; j < 8; j++) s[j] = __ldg(srcs + i + j);
#pragma unroll
        for (int j = 0; j < 8; j++) e[j] = __ldg(elm + s[j]*NH + h);
#pragma unroll
        for (int j = 0; j < 8; j++) f[j] = *(const uint32_t*)(featm + (size_t)s[j]*HDIM + dimo);
#pragma unroll
        for (int j = 0; j < 8; j++) {
            float ev = e[j] + ern;
            ev = (ev > 0.f) ? ev : 0.2f*ev;
            float x = __expf(ev);
            float2 u = __bfloat1622float2(*(__nv_bfloat162*)&f[j]);
            if (j & 1) { dn2 += x; bx += x*u.x; by += x*u.y; }
            else       { den += x; ax += x*u.x; ay += x*u.y; }
        }
    }
    for (; i + 2 <= end; i += 2) {
        int s0 = __ldg(srcs + i), s1 = __ldg(srcs + i + 1);
        float e0 = __ldg(elm + s0*NH + h) + ern;
        float e1 = __ldg(elm + s1*NH + h) + ern;
        uint32_t f0 = *(const uint32_t*)(featm + (size_t)s0*HDIM + dimo);
        uint32_t f1 = *(const uint32_t*)(featm + (size_t)s1*HDIM + dimo);
        e0 = (e0 > 0.f) ? e0 : 0.2f*e0;
        e1 = (e1 > 0.f) ? e1 : 0.2f*e1;
        float x0 = __expf(e0), x1 = __expf(e1);
        den += x0; dn2 += x1;
        float2 u = __bfloat1622float2(*(__nv_bfloat162*)&f0);
        float2 v2 = __bfloat1622float2(*(__nv_bfloat162*)&f1);
        ax += x0*u.x; ay += x0*u.y;
        bx += x1*v2.x; by += x1*v2.y;
    }
    if (i < end) {
        int s0 = __ldg(srcs + i);
        float e0 = __ldg(elm + s0*NH + h) + ern;
        uint32_t f0 = *(const uint32_t*)(featm + (size_t)s0*HDIM + dimo);
        e0 = (e0 > 0.f) ? e0 : 0.2f*e0;
        float x0 = __expf(e0);
        den += x0;
        float2 u = __bfloat1622float2(*(__nv_bfloat162*)&f0);
        ax += x0*u.x; ay += x0*u.y;
    }
    den += dn2; ax += bx; ay += by;
    float inv = (end > beg) ? 1.f/den : 0.f;
    float2 o; float v;
    v = ax*inv; o.x = (v > 0.f) ? v : expm1f(v);
    v = ay*inv; o.y = (v > 0.f) ? v : expm1f(v);
    *(float2*)(g_z + (size_t)(n*MM + m)*HDIM + dimo) = o;
}

// ---- tail: s = exp(w); fus += s*z; den += s ----
__global__ __launch_bounds__(384) void k_tail() {
    int t = threadIdx.x, ms = t >> 7;
    float acc = 0.f, dloc = 0.f;
    for (int n = blockIdx.x; n < NN; n += gridDim.x) {
        float s = __expf(g_w[n*3 + ms]);
        acc += s * g_z[(size_t)n*ZROW + t];
        dloc += s;
    }
    atomicAdd(&g_fus[t], acc);
    if ((t & 127) == 0) atomicAdd(&g_den[ms], dloc);
}

__global__ void k_final(const float* __restrict__ PW, const float* __restrict__ PB,
                        float* __restrict__ out) {
    int t = threadIdx.x;
    if (t >= MM*OUTC) return;
    int m = t / OUTC, o = t - m*OUTC;
    float a = 0.f;
#pragma unroll 8
    for (int c = 0; c < HDIM; c++) a += g_fus[m*HDIM + c] * __ldg(PW + c*OUTC + o);
    out[t] = a / g_den[m] + __ldg(PB + o);
}

extern "C" void kernel_launch(void* const* d_in, const int* in_sizes, int n_in,
                              void* d_out, int out_size) {
    const float* h      = (const float*)d_in[0];
    const int*   edges  = (const int*)d_in[1];
    const float* fc_w   = (const float*)d_in[2];
    const float* attn_l = (const float*)d_in[3];
    const float* attn_r = (const float*)d_in[4];
    const float* sa_w1  = (const float*)d_in[5];
    const float* sa_b1  = (const float*)d_in[6];
    const float* sa_w2  = (const float*)d_in[7];
    const float* pred_w = (const float*)d_in[8];
    const float* pred_b = (const float*)d_in[9];
    float* out = (float*)d_out;

    static int inited = 0;
    static cudaStream_t s2;
    static cudaEvent_t ev_fork, ev_join;
    if (!inited) {
        cudaFuncSetAttribute(k_feat_mma, cudaFuncAttributeMaxDynamicSharedMemorySize, FEAT_DYN);
        cudaStreamCreateWithFlags(&s2, cudaStreamNonBlocking);
        cudaEventCreateWithFlags(&ev_fork, cudaEventDisableTiming);
        cudaEventCreateWithFlags(&ev_join, cudaEventDisableTiming);
        inited = 1;
    }

    cudaEventRecord(ev_fork, 0);
    cudaStreamWaitEvent(s2, ev_fork, 0);
    k_init<<<(MM*NN + 255)/256, 256, 0, s2>>>();
    k_hist<<<(MM*EE + 255)/256, 256, 0, s2>>>(edges);
    k_scan<<<MM, 1024, 0, s2>>>();
    k_scatter<<<(MM*EE + 255)/256, 256, 0, s2>>>(edges);
    cudaEventRecord(ev_join, s2);

    k_prep<<<(MM*HDIM*INSZ + SAH*HDIM + MM*HDIM + MM + 255)/256, 256>>>(fc_w, sa_w1);
    k_feat_mma<<<dim3((NN + 127)/128, MM), 256, FEAT_DYN>>>(h, attn_l, attn_r);

    cudaStreamWaitEvent(0, ev_join, 0);
    k_agg<<<dim3((2*NN + 7)/8, MM), 256>>>();
    k_sa_mma<<<(SAROWS + 127)/128, 256>>>(sa_b1, sa_w2);
    k_tail<<<256, 384>>>();
    k_final<<<1, 32>>>(pred_w, pred_b, out);
}

// round 15
// speedup vs baseline: 1.1027x; 1.1027x over previous
#include <cuda_runtime.h>
#include <cuda_bf16.h>
#include <math.h>
#include <stdint.h>

#define NN   50000
#define EE   800000
#define MM   3
#define INSZ 256
#define HDIM 128
#define NH   8
#define DH   16
#define OUTC 8
#define SAH  128
#define ZROW (MM*HDIM)
#define SAROWS (NN*MM)
#define FSTR 36
#define FEAT_DYN (4*128*FSTR*4)

__device__ __align__(16) __nv_bfloat16 g_feat16[(size_t)MM*NN*HDIM];
__device__ __align__(16) float g_z[(size_t)SAROWS*HDIM];
__device__ float g_el[MM*NN*NH];
__device__ float g_er[MM*NN*NH];
__device__ int   g_deg[MM*NN];
__device__ int   g_off[MM*(NN+1)];
__device__ int   g_cur[MM*NN];
__device__ int   g_srt[MM*EE];
__device__ float g_w[SAROWS];
__device__ float g_den[MM];
__device__ float g_fus[MM*HDIM];
__device__ __align__(16) float g_wt[MM*HDIM*INSZ];
__device__ __align__(16) float g_w1t[SAH*HDIM];

__device__ __forceinline__ uint32_t smem_u32(const void* p) {
    uint32_t a;
    asm("{ .reg .u64 t; cvta.to.shared.u64 t, %1; cvt.u32.u64 %0, t; }" : "=r"(a) : "l"(p));
    return a;
}
__device__ __forceinline__ void cp_async16(uint32_t saddr, const void* g) {
    asm volatile("cp.async.cg.shared.global [%0], [%1], 16;" :: "r"(saddr), "l"(g));
}
__device__ __forceinline__ void cp_async16z(uint32_t saddr, const void* g, int sz) {
    asm volatile("cp.async.cg.shared.global [%0], [%1], 16, %2;" :: "r"(saddr), "l"(g), "r"(sz));
}
#define CP_COMMIT() asm volatile("cp.async.commit_group;" ::: "memory")
#define CP_WAIT0()  asm volatile("cp.async.wait_group 0;" ::: "memory")
#define CP_WAIT1()  asm volatile("cp.async.wait_group 1;" ::: "memory")
__device__ __forceinline__ uint32_t tf32r_u(float x) {
    uint32_t u;
    asm("cvt.rna.tf32.f32 %0, %1;" : "=r"(u) : "f"(x));
    return u;
}
__device__ __forceinline__ void mma_tf32(float* c, const uint32_t* a, uint32_t b0, uint32_t b1) {
    asm volatile("mma.sync.aligned.m16n8k8.row.col.f32.tf32.tf32.f32 "
        "{%0,%1,%2,%3}, {%4,%5,%6,%7}, {%8,%9}, {%0,%1,%2,%3};"
        : "+f"(c[0]), "+f"(c[1]), "+f"(c[2]), "+f"(c[3])
        : "r"(a[0]), "r"(a[1]), "r"(a[2]), "r"(a[3]), "r"(b0), "r"(b1));
}

__global__ void k_init() {
    int idx = blockIdx.x * blockDim.x + threadIdx.x;
    if (idx < MM*NN) g_deg[idx] = 0;
}

__global__ void k_prep(const float* __restrict__ fc_w, const float* __restrict__ sa_w1) {
    int idx = blockIdx.x * blockDim.x + threadIdx.x;
    if (idx < MM*HDIM*INSZ) {
        int m = idx / (HDIM*INSZ), r = idx - m*(HDIM*INSZ);
        int n = r / INSZ, k = r - n*INSZ;
        g_wt[idx] = __uint_as_float(tf32r_u(fc_w[((size_t)m*INSZ + k)*HDIM + n]));
    } else {
        int j = idx - MM*HDIM*INSZ;
        if (j < SAH*HDIM) {
            int n = j / HDIM, k = j - n*HDIM;
            g_w1t[j] = __uint_as_float(tf32r_u(sa_w1[(size_t)k*SAH + n]));
        } else {
            int q = j - SAH*HDIM;
            if (q < MM*HDIM) g_fus[q] = 0.f;
            else if (q < MM*HDIM + MM) g_den[q - MM*HDIM] = 0.f;
        }
    }
}

// ---- feat = h @ fc_w[m], tf32 mma, double-buffered cp.async pipeline ----
__global__ __launch_bounds__(256, 2) void k_feat_mma(const float* __restrict__ A,
                                                     const float* __restrict__ AL,
                                                     const float* __restrict__ AR) {
    extern __shared__ __align__(16) float smf[];
    float* sA = smf;
    float* sB = smf + 2*128*FSTR;
    __shared__ float s_al[128], s_ar[128];
    int tid = threadIdx.x, w = tid >> 5, lane = tid & 31;
    int wm = w >> 1, wn = w & 1, g = lane >> 2, t4 = lane & 3;
    int m = blockIdx.y, row0 = blockIdx.x * 128;
    if (tid < 128) { s_al[tid] = AL[m*HDIM + tid]; s_ar[tid] = AR[m*HDIM + tid]; }
    float acc[2][8][4];
#pragma unroll
    for (int mt = 0; mt < 2; mt++)
#pragma unroll
        for (int j = 0; j < 8; j++)
#pragma unroll
            for (int i = 0; i < 4; i++) acc[mt][j][i] = 0.f;

    const float* Bm = g_wt + (size_t)m * HDIM * INSZ;
    int r_ld = tid >> 3, q_ld = tid & 7;

    auto stage = [&](int kc, int buf) {
        int k0 = kc * 32;
        uint32_t aA = smem_u32(sA + buf*128*FSTR);
        uint32_t aB = smem_u32(sB + buf*128*FSTR);
#pragma unroll
        for (int i = 0; i < 4; i++) {
            int r = r_ld + i*32, q = q_ld;
            int node = row0 + r;
            const float* src = A + (size_t)(node < NN ? node : 0) * INSZ + k0 + q * 4;
            cp_async16z(aA + (uint32_t)(r*FSTR + q*4)*4, src, node < NN ? 16 : 0);
            cp_async16(aB + (uint32_t)(r*FSTR + q*4)*4, Bm + (size_t)r * INSZ + k0 + q * 4);
        }
        CP_COMMIT();
    };

    stage(0, 0);
    for (int kc = 0; kc < 8; kc++) {
        if (kc < 7) { stage(kc + 1, (kc + 1) & 1); CP_WAIT1(); }
        else        { CP_WAIT0(); }
        __syncthreads();
        const float* sAb = sA + (kc & 1)*128*FSTR;
        const float* sBb = sB + (kc & 1)*128*FSTR;
#pragma unroll
        for (int ks = 0; ks < 4; ks++) {
            int kb = ks * 8;
            uint32_t af[2][4];
#pragma unroll
            for (int mt = 0; mt < 2; mt++) {
                int ar_ = wm*32 + mt*16 + g;
                af[mt][0] = tf32r_u(sAb[ar_*FSTR + kb + t4]);
                af[mt][1] = tf32r_u(sAb[(ar_+8)*FSTR + kb + t4]);
                af[mt][2] = tf32r_u(sAb[ar_*FSTR + kb + t4 + 4]);
                af[mt][3] = tf32r_u(sAb[(ar_+8)*FSTR + kb + t4 + 4]);
            }
#pragma unroll
            for (int jp = 0; jp < 8; jp++) {
                int bn = wn*64 + jp*8 + g;
                uint32_t b0 = __float_as_uint(sBb[bn*FSTR + kb + t4]);
                uint32_t b1 = __float_as_uint(sBb[bn*FSTR + kb + t4 + 4]);
                mma_tf32(acc[0][jp], af[0], b0, b1);
                mma_tf32(acc[1][jp], af[1], b0, b1);
            }
        }
        __syncthreads();
    }
    __nv_bfloat16* outp = g_feat16 + (size_t)m * NN * HDIM;
#pragma unroll
    for (int mt = 0; mt < 2; mt++) {
        int r0 = row0 + wm*32 + mt*16 + g;
#pragma unroll
        for (int jp = 0; jp < 8; jp++) {
            int col = wn*64 + jp*8 + t4*2;
            if (r0 < NN)
                *(__nv_bfloat162*)(outp + (size_t)r0 * HDIM + col) =
                    __float22bfloat162_rn(make_float2(acc[mt][jp][0], acc[mt][jp][1]));
            if (r0 + 8 < NN)
                *(__nv_bfloat162*)(outp + (size_t)(r0 + 8) * HDIM + col) =
                    __float22bfloat162_rn(make_float2(acc[mt][jp][2], acc[mt][jp][3]));
        }
#pragma unroll
        for (int hh = 0; hh < 4; hh++) {
            float pl0 = 0.f, pr0 = 0.f, pl1 = 0.f, pr1 = 0.f;
#pragma unroll
            for (int jj = 2*hh; jj <= 2*hh+1; jj++) {
                int c0 = wn*64 + jj*8 + t4*2, c1 = c0 + 1;
                float a0 = s_al[c0], a1 = s_al[c1], b0 = s_ar[c0], b1 = s_ar[c1];
                pl0 += acc[mt][jj][0]*a0 + acc[mt][jj][1]*a1;
                pr0 += acc[mt][jj][0]*b0 + acc[mt][jj][1]*b1;
                pl1 += acc[mt][jj][2]*a0 + acc[mt][jj][3]*a1;
                pr1 += acc[mt][jj][2]*b0 + acc[mt][jj][3]*b1;
            }
            pl0 += __shfl_xor_sync(0xffffffffu, pl0, 1); pl0 += __shfl_xor_sync(0xffffffffu, pl0, 2);
            pr0 += __shfl_xor_sync(0xffffffffu, pr0, 1); pr0 += __shfl_xor_sync(0xffffffffu, pr0, 2);
            pl1 += __shfl_xor_sync(0xffffffffu, pl1, 1); pl1 += __shfl_xor_sync(0xffffffffu, pl1, 2);
            pr1 += __shfl_xor_sync(0xffffffffu, pr1, 1); pr1 += __shfl_xor_sync(0xffffffffu, pr1, 2);
            if (t4 == 0) {
                int h = wn*4 + hh;
                if (r0 < NN) {
                    g_el[(m*NN + r0)*NH + h] = pl0;
                    g_er[(m*NN + r0)*NH + h] = pr0;
                }
                if (r0 + 8 < NN) {
                    g_el[(m*NN + r0 + 8)*NH + h] = pl1;
                    g_er[(m*NN + r0 + 8)*NH + h] = pr1;
                }
            }
        }
    }
}

// ---- SA GEMM tf32 + fused tanh epilogue ----
__global__ __launch_bounds__(256, 2) void k_sa_mma(const float* __restrict__ B1,
                                                   const float* __restrict__ W2) {
    __shared__ __align__(16) float sA[128*FSTR], sB[128*FSTR];
    __shared__ float s_b1[128], s_w2[128];
    int tid = threadIdx.x, w = tid >> 5, lane = tid & 31;
    int g = lane >> 2, t4 = lane & 3;
    int row0 = blockIdx.x * 128;
    if (tid < 128) { s_b1[tid] = B1[tid]; s_w2[tid] = W2[tid]; }
    uint32_t aA = smem_u32(sA), aB = smem_u32(sB);
    float acc[16][4];
#pragma unroll
    for (int j = 0; j < 16; j++)
#pragma unroll
        for (int i = 0; i < 4; i++) acc[j][i] = 0.f;

    for (int kc = 0; kc < 4; kc++) {
        int k0 = kc * 32;
#pragma unroll
        for (int i = 0; i < 4; i++) {
            int p = i * 256 + tid;
            int r = p >> 3, q = p & 7;
            int row = row0 + r;
            const float* src = g_z + (size_t)(row < SAROWS ? row : 0) * HDIM + k0 + q * 4;
            cp_async16z(aA + (uint32_t)(r*FSTR + q*4)*4, src, row < SAROWS ? 16 : 0);
            cp_async16(aB + (uint32_t)(r*FSTR + q*4)*4, g_w1t + (size_t)r * HDIM + k0 + q * 4);
        }
        CP_COMMIT();
        CP_WAIT0();
        __syncthreads();
#pragma unroll
        for (int ks = 0; ks < 4; ks++) {
            int kb = ks * 8;
            int ar_ = w*16 + g;
            uint32_t af[4];
            af[0] = tf32r_u(sA[ar_*FSTR + kb + t4]);
            af[1] = tf32r_u(sA[(ar_+8)*FSTR + kb + t4]);
            af[2] = tf32r_u(sA[ar_*FSTR + kb + t4 + 4]);
            af[3] = tf32r_u(sA[(ar_+8)*FSTR + kb + t4 + 4]);
#pragma unroll
            for (int jp = 0; jp < 16; jp++) {
                int bn = jp*8 + g;
                uint32_t b0 = __float_as_uint(sB[bn*FSTR + kb + t4]);
                uint32_t b1 = __float_as_uint(sB[bn*FSTR + kb + t4 + 4]);
                mma_tf32(acc[jp], af, b0, b1);
            }
        }
        __syncthreads();
    }
    float s0 = 0.f, s1 = 0.f;
#pragma unroll
    for (int j = 0; j < 16; j++) {
        int col = j * 8 + t4 * 2;
        float b0 = s_b1[col], b1v = s_b1[col + 1];
        float w0 = s_w2[col], w1v = s_w2[col + 1];
        s0 += tanhf(acc[j][0] + b0) * w0 + tanhf(acc[j][1] + b1v) * w1v;
        s1 += tanhf(acc[j][2] + b0) * w0 + tanhf(acc[j][3] + b1v) * w1v;
    }
    s0 += __shfl_xor_sync(0xffffffffu, s0, 1); s0 += __shfl_xor_sync(0xffffffffu, s0, 2);
    s1 += __shfl_xor_sync(0xffffffffu, s1, 1); s1 += __shfl_xor_sync(0xffffffffu, s1, 2);
    if (t4 == 0) {
        int r0 = row0 + w * 16 + g;
        if (r0 < SAROWS)     g_w[r0]     = s0;
        if (r0 + 8 < SAROWS) g_w[r0 + 8] = s1;
    }
}

// ---- CSR build: scalar 1 edge/thread ----
__global__ void k_hist(const int* __restrict__ edges) {
    int idx = blockIdx.x * blockDim.x + threadIdx.x;
    if (idx >= MM*EE) return;
    int m = idx / EE, e = idx - m*EE;
    atomicAdd(&g_deg[m*NN + edges[(size_t)m*2*EE + EE + e]], 1);
}

__global__ void k_scan() {
    __shared__ int sh[1024];
    int m = blockIdx.x, t = threadIdx.x;
    const int CH = (NN + 1023) / 1024;
    int base = t * CH, sum = 0;
    for (int i = 0; i < CH; i++) { int idx = base+i; if (idx < NN) sum += g_deg[m*NN+idx]; }
    sh[t] = sum; __syncthreads();
    for (int d = 1; d < 1024; d <<= 1) {
        int v = (t >= d) ? sh[t-d] : 0; __syncthreads();
        sh[t] += v; __syncthreads();
    }
    int run = sh[t] - sum;
    for (int i = 0; i < CH; i++) {
        int idx = base+i;
        if (idx < NN) { g_off[m*(NN+1)+idx] = run; g_cur[m*NN+idx] = run; run += g_deg[m*NN+idx]; }
    }
    if (t == 1023) g_off[m*(NN+1)+NN] = sh[1023];
}

__global__ void k_scatter(const int* __restrict__ edges) {
    int idx = blockIdx.x * blockDim.x + threadIdx.x;
    if (idx >= MM*EE) return;
    int m = idx / EE, e = idx - m*EE;
    int src = edges[(size_t)m*2*EE + e];
    int dst = edges[(size_t)m*2*EE + EE + e];
    g_srt[(size_t)m*EE + atomicAdd(&g_cur[m*NN + dst], 1)] = src;
}

// ---- GAT aggregation: warp/dst, unroll-8 + next-batch srcs prefetch ----
__global__ __launch_bounds__(256) void k_agg() {
    int lane = threadIdx.x & 31;
    int wid  = (blockIdx.x * blockDim.x + threadIdx.x) >> 5;
    int m    = blockIdx.y;
    if (wid >= NN) return;
    int n = wid, h = lane >> 2;
    int beg = g_off[m*(NN+1)+n], end = g_off[m*(NN+1)+n+1];
    float ern = g_er[(m*NN+n)*NH + h];
    const __nv_bfloat16* featm = g_feat16 + (size_t)m*HDIM*NN;
    const float* elm = g_el + m*NN*NH;
    const int*   srcs = g_srt + (size_t)m*EE;
    float den = 0.f, ax = 0.f, ay = 0.f, az = 0.f, aw = 0.f;
    float dn2 = 0.f, bx = 0.f, by = 0.f, bz = 0.f, bw = 0.f;
    int i = beg;
    if (i + 8 <= end) {
        int s[8];
#pragma unroll
        for (int j = 0; j < 8; j++) s[j] = __ldg(srcs + i + j);
        for (; i + 8 <= end; ) {
            float e[8]; uint2 f[8];
#pragma unroll
            for (int j = 0; j < 8; j++) e[j] = __ldg(elm + s[j]*NH + h);
#pragma unroll
            for (int j = 0; j < 8; j++) f[j] = *(const uint2*)(featm + (size_t)s[j]*HDIM + lane*4);
            i += 8;
            if (i + 8 <= end) {   // prefetch next batch's indices before math
#pragma unroll
                for (int j = 0; j < 8; j++) s[j] = __ldg(srcs + i + j);
            }
#pragma unroll
            for (int j = 0; j < 8; j++) {
                float ev = e[j] + ern;
                ev = (ev > 0.f) ? ev : 0.2f*ev;
                float x = __expf(ev);
                float2 u0 = __bfloat1622float2(*(__nv_bfloat162*)&f[j].x);
                float2 u1 = __bfloat1622float2(*(__nv_bfloat162*)&f[j].y);
                if (j & 1) { dn2 += x; bx += x*u0.x; by += x*u0.y; bz += x*u1.x; bw += x*u1.y; }
                else       { den += x; ax += x*u0.x; ay += x*u0.y; az += x*u1.x; aw += x*u1.y; }
            }
        }
    }
    for (; i + 2 <= end; i += 2) {
        int s0 = __ldg(srcs + i), s1 = __ldg(srcs + i + 1);
        float e0 = __ldg(elm + s0*NH + h) + ern;
        float e1 = __ldg(elm + s1*NH + h) + ern;
        uint2 f0 = *(const uint2*)(featm + (size_t)s0*HDIM + lane*4);
        uint2 f1 = *(const uint2*)(featm + (size_t)s1*HDIM + lane*4);
        e0 = (e0 > 0.f) ? e0 : 0.2f*e0;
        e1 = (e1 > 0.f) ? e1 : 0.2f*e1;
        float x0 = __expf(e0), x1 = __expf(e1);
        den += x0; dn2 += x1;
        float2 u0 = __bfloat1622float2(*(__nv_bfloat162*)&f0.x);
        float2 u1 = __bfloat1622float2(*(__nv_bfloat162*)&f0.y);
        float2 v0 = __bfloat1622float2(*(__nv_bfloat162*)&f1.x);
        float2 v1 = __bfloat1622float2(*(__nv_bfloat162*)&f1.y);
        ax += x0*u0.x; ay += x0*u0.y; az += x0*u1.x; aw += x0*u1.y;
        bx += x1*v0.x; by += x1*v0.y; bz += x1*v1.x; bw += x1*v1.y;
    }
    if (i < end) {
        int s0 = __ldg(srcs + i);
        float e0 = __ldg(elm + s0*NH + h) + ern;
        uint2 f0 = *(const uint2*)(featm + (size_t)s0*HDIM + lane*4);
        e0 = (e0 > 0.f) ? e0 : 0.2f*e0;
        float x0 = __expf(e0);
        den += x0;
        float2 u0 = __bfloat1622float2(*(__nv_bfloat162*)&f0.x);
        float2 u1 = __bfloat1622float2(*(__nv_bfloat162*)&f0.y);
        ax += x0*u0.x; ay += x0*u0.y; az += x0*u1.x; aw += x0*u1.y;
    }
    den += dn2; ax += bx; ay += by; az += bz; aw += bw;
    float inv = (end > beg) ? 1.f/den : 0.f;
    float4 o; float v;
    v = ax*inv; o.x = (v > 0.f) ? v : expm1f(v);
    v = ay*inv; o.y = (v > 0.f) ? v : expm1f(v);
    v = az*inv; o.z = (v > 0.f) ? v : expm1f(v);
    v = aw*inv; o.w = (v > 0.f) ? v : expm1f(v);
    *(float4*)(g_z + (size_t)(n*MM + m)*HDIM + lane*4) = o;
}

// ---- tail: s = exp(w); fus += s*z; den += s ----
__global__ __launch_bounds__(384) void k_tail() {
    int t = threadIdx.x, ms = t >> 7;
    float acc = 0.f, dloc = 0.f;
    for (int n = blockIdx.x; n < NN; n += gridDim.x) {
        float s = __expf(g_w[n*3 + ms]);
        acc += s * g_z[(size_t)n*ZROW + t];
        dloc += s;
    }
    atomicAdd(&g_fus[t], acc);
    if ((t & 127) == 0) atomicAdd(&g_den[ms], dloc);
}

__global__ void k_final(const float* __restrict__ PW, const float* __restrict__ PB,
                        float* __restrict__ out) {
    int t = threadIdx.x;
    if (t >= MM*OUTC) return;
    int m = t / OUTC, o = t - m*OUTC;
    float a = 0.f;
#pragma unroll 8
    for (int c = 0; c < HDIM; c++) a += g_fus[m*HDIM + c] * __ldg(PW + c*OUTC + o);
    out[t] = a / g_den[m] + __ldg(PB + o);
}

extern "C" void kernel_launch(void* const* d_in, const int* in_sizes, int n_in,
                              void* d_out, int out_size) {
    const float* h      = (const float*)d_in[0];
    const int*   edges  = (const int*)d_in[1];
    const float* fc_w   = (const float*)d_in[2];
    const float* attn_l = (const float*)d_in[3];
    const float* attn_r = (const float*)d_in[4];
    const float* sa_w1  = (const float*)d_in[5];
    const float* sa_b1  = (const float*)d_in[6];
    const float* sa_w2  = (const float*)d_in[7];
    const float* pred_w = (const float*)d_in[8];
    const float* pred_b = (const float*)d_in[9];
    float* out = (float*)d_out;

    static int inited = 0;
    static cudaStream_t s2;
    static cudaEvent_t ev_fork, ev_join;
    if (!inited) {
        cudaFuncSetAttribute(k_feat_mma, cudaFuncAttributeMaxDynamicSharedMemorySize, FEAT_DYN);
        cudaStreamCreateWithFlags(&s2, cudaStreamNonBlocking);
        cudaEventCreateWithFlags(&ev_fork, cudaEventDisableTiming);
        cudaEventCreateWithFlags(&ev_join, cudaEventDisableTiming);
        inited = 1;
    }

    cudaEventRecord(ev_fork, 0);
    cudaStreamWaitEvent(s2, ev_fork, 0);
    k_init<<<(MM*NN + 255)/256, 256, 0, s2>>>();
    k_hist<<<(MM*EE + 255)/256, 256, 0, s2>>>(edges);
    k_scan<<<MM, 1024, 0, s2>>>();
    k_scatter<<<(MM*EE + 255)/256, 256, 0, s2>>>(edges);
    cudaEventRecord(ev_join, s2);

    k_prep<<<(MM*HDIM*INSZ + SAH*HDIM + MM*HDIM + MM + 255)/256, 256>>>(fc_w, sa_w1);
    k_feat_mma<<<dim3((NN + 127)/128, MM), 256, FEAT_DYN>>>(h, attn_l, attn_r);

    cudaStreamWaitEvent(0, ev_join, 0);
    k_agg<<<dim3((NN + 7)/8, MM), 256>>>();
    k_sa_mma<<<(SAROWS + 127)/128, 256>>>(sa_b1, sa_w2);
    k_tail<<<256, 384>>>();
    k_final<<<1, 32>>>(pred_w, pred_b, out);
}

// round 16
// speedup vs baseline: 1.1466x; 1.0398x over previous
#include <cuda_runtime.h>
#include <cuda_bf16.h>
#include <math.h>
#include <stdint.h>

#define NN   50000
#define EE   800000
#define MM   3
#define INSZ 256
#define HDIM 128
#define NH   8
#define DH   16
#define OUTC 8
#define SAH  128
#define ZROW (MM*HDIM)
#define SAROWS (NN*MM)
#define FSTR 36
#define FEAT_DYN (4*128*FSTR*4)
#define TAIL_GRID 256

__device__ __align__(16) __nv_bfloat16 g_feat16[(size_t)MM*NN*HDIM];
__device__ __align__(16) float g_z[(size_t)SAROWS*HDIM];
__device__ float g_el[MM*NN*NH];
__device__ float g_er[MM*NN*NH];
__device__ int   g_deg[MM*NN];
__device__ int   g_off[MM*(NN+1)];
__device__ int   g_cur[MM*NN];
__device__ int   g_srt[MM*EE];
__device__ float g_w[SAROWS];
__device__ float g_den[MM];
__device__ float g_fus[MM*HDIM];
__device__ int   g_ctr;
__device__ __align__(16) float g_wt[MM*HDIM*INSZ];
__device__ __align__(16) float g_w1t[SAH*HDIM];

__device__ __forceinline__ uint32_t smem_u32(const void* p) {
    uint32_t a;
    asm("{ .reg .u64 t; cvta.to.shared.u64 t, %1; cvt.u32.u64 %0, t; }" : "=r"(a) : "l"(p));
    return a;
}
__device__ __forceinline__ void cp_async16(uint32_t saddr, const void* g) {
    asm volatile("cp.async.cg.shared.global [%0], [%1], 16;" :: "r"(saddr), "l"(g));
}
__device__ __forceinline__ void cp_async16z(uint32_t saddr, const void* g, int sz) {
    asm volatile("cp.async.cg.shared.global [%0], [%1], 16, %2;" :: "r"(saddr), "l"(g), "r"(sz));
}
#define CP_COMMIT() asm volatile("cp.async.commit_group;" ::: "memory")
#define CP_WAIT0()  asm volatile("cp.async.wait_group 0;" ::: "memory")
#define CP_WAIT1()  asm volatile("cp.async.wait_group 1;" ::: "memory")
__device__ __forceinline__ uint32_t tf32r_u(float x) {
    uint32_t u;
    asm("cvt.rna.tf32.f32 %0, %1;" : "=r"(u) : "f"(x));
    return u;
}
__device__ __forceinline__ void mma_tf32(float* c, const uint32_t* a, uint32_t b0, uint32_t b1) {
    asm volatile("mma.sync.aligned.m16n8k8.row.col.f32.tf32.tf32.f32 "
        "{%0,%1,%2,%3}, {%4,%5,%6,%7}, {%8,%9}, {%0,%1,%2,%3};"
        : "+f"(c[0]), "+f"(c[1]), "+f"(c[2]), "+f"(c[3])
        : "r"(a[0]), "r"(a[1]), "r"(a[2]), "r"(a[3]), "r"(b0), "r"(b1));
}

__global__ void k_init() {
    int idx = blockIdx.x * blockDim.x + threadIdx.x;
    if (idx < MM*NN) g_deg[idx] = 0;
}

__global__ void k_prep(const float* __restrict__ fc_w, const float* __restrict__ sa_w1) {
    int idx = blockIdx.x * blockDim.x + threadIdx.x;
    if (idx < MM*HDIM*INSZ) {
        int m = idx / (HDIM*INSZ), r = idx - m*(HDIM*INSZ);
        int n = r / INSZ, k = r - n*INSZ;
        g_wt[idx] = __uint_as_float(tf32r_u(fc_w[((size_t)m*INSZ + k)*HDIM + n]));
    } else {
        int j = idx - MM*HDIM*INSZ;
        if (j < SAH*HDIM) {
            int n = j / HDIM, k = j - n*HDIM;
            g_w1t[j] = __uint_as_float(tf32r_u(sa_w1[(size_t)k*SAH + n]));
        } else {
            int q = j - SAH*HDIM;
            if (q < MM*HDIM) g_fus[q] = 0.f;
            else if (q < MM*HDIM + MM) g_den[q - MM*HDIM] = 0.f;
            else if (q == MM*HDIM + MM) g_ctr = 0;
        }
    }
}

// ---- feat = h @ fc_w[m], tf32 mma, double-buffered cp.async pipeline ----
__global__ __launch_bounds__(256, 2) void k_feat_mma(const float* __restrict__ A,
                                                     const float* __restrict__ AL,
                                                     const float* __restrict__ AR) {
    extern __shared__ __align__(16) float smf[];
    float* sA = smf;
    float* sB = smf + 2*128*FSTR;
    __shared__ float s_al[128], s_ar[128];
    int tid = threadIdx.x, w = tid >> 5, lane = tid & 31;
    int wm = w >> 1, wn = w & 1, g = lane >> 2, t4 = lane & 3;
    int m = blockIdx.y, row0 = blockIdx.x * 128;
    if (tid < 128) { s_al[tid] = AL[m*HDIM + tid]; s_ar[tid] = AR[m*HDIM + tid]; }
    float acc[2][8][4];
#pragma unroll
    for (int mt = 0; mt < 2; mt++)
#pragma unroll
        for (int j = 0; j < 8; j++)
#pragma unroll
            for (int i = 0; i < 4; i++) acc[mt][j][i] = 0.f;

    const float* Bm = g_wt + (size_t)m * HDIM * INSZ;
    int r_ld = tid >> 3, q_ld = tid & 7;

    auto stage = [&](int kc, int buf) {
        int k0 = kc * 32;
        uint32_t aA = smem_u32(sA + buf*128*FSTR);
        uint32_t aB = smem_u32(sB + buf*128*FSTR);
#pragma unroll
        for (int i = 0; i < 4; i++) {
            int r = r_ld + i*32, q = q_ld;
            int node = row0 + r;
            const float* src = A + (size_t)(node < NN ? node : 0) * INSZ + k0 + q * 4;
            cp_async16z(aA + (uint32_t)(r*FSTR + q*4)*4, src, node < NN ? 16 : 0);
            cp_async16(aB + (uint32_t)(r*FSTR + q*4)*4, Bm + (size_t)r * INSZ + k0 + q * 4);
        }
        CP_COMMIT();
    };

    stage(0, 0);
    for (int kc = 0; kc < 8; kc++) {
        if (kc < 7) { stage(kc + 1, (kc + 1) & 1); CP_WAIT1(); }
        else        { CP_WAIT0(); }
        __syncthreads();
        const float* sAb = sA + (kc & 1)*128*FSTR;
        const float* sBb = sB + (kc & 1)*128*FSTR;
#pragma unroll
        for (int ks = 0; ks < 4; ks++) {
            int kb = ks * 8;
            uint32_t af[2][4];
#pragma unroll
            for (int mt = 0; mt < 2; mt++) {
                int ar_ = wm*32 + mt*16 + g;
                af[mt][0] = tf32r_u(sAb[ar_*FSTR + kb + t4]);
                af[mt][1] = tf32r_u(sAb[(ar_+8)*FSTR + kb + t4]);
                af[mt][2] = tf32r_u(sAb[ar_*FSTR + kb + t4 + 4]);
                af[mt][3] = tf32r_u(sAb[(ar_+8)*FSTR + kb + t4 + 4]);
            }
#pragma unroll
            for (int jp = 0; jp < 8; jp++) {
                int bn = wn*64 + jp*8 + g;
                uint32_t b0 = __float_as_uint(sBb[bn*FSTR + kb + t4]);
                uint32_t b1 = __float_as_uint(sBb[bn*FSTR + kb + t4 + 4]);
                mma_tf32(acc[0][jp], af[0], b0, b1);
                mma_tf32(acc[1][jp], af[1], b0, b1);
            }
        }
        __syncthreads();
    }
    __nv_bfloat16* outp = g_feat16 + (size_t)m * NN * HDIM;
#pragma unroll
    for (int mt = 0; mt < 2; mt++) {
        int r0 = row0 + wm*32 + mt*16 + g;
#pragma unroll
        for (int jp = 0; jp < 8; jp++) {
            int col = wn*64 + jp*8 + t4*2;
            if (r0 < NN)
                *(__nv_bfloat162*)(outp + (size_t)r0 * HDIM + col) =
                    __float22bfloat162_rn(make_float2(acc[mt][jp][0], acc[mt][jp][1]));
            if (r0 + 8 < NN)
                *(__nv_bfloat162*)(outp + (size_t)(r0 + 8) * HDIM + col) =
                    __float22bfloat162_rn(make_float2(acc[mt][jp][2], acc[mt][jp][3]));
        }
#pragma unroll
        for (int hh = 0; hh < 4; hh++) {
            float pl0 = 0.f, pr0 = 0.f, pl1 = 0.f, pr1 = 0.f;
#pragma unroll
            for (int jj = 2*hh; jj <= 2*hh+1; jj++) {
                int c0 = wn*64 + jj*8 + t4*2, c1 = c0 + 1;
                float a0 = s_al[c0], a1 = s_al[c1], b0 = s_ar[c0], b1 = s_ar[c1];
                pl0 += acc[mt][jj][0]*a0 + acc[mt][jj][1]*a1;
                pr0 += acc[mt][jj][0]*b0 + acc[mt][jj][1]*b1;
                pl1 += acc[mt][jj][2]*a0 + acc[mt][jj][3]*a1;
                pr1 += acc[mt][jj][2]*b0 + acc[mt][jj][3]*b1;
            }
            pl0 += __shfl_xor_sync(0xffffffffu, pl0, 1); pl0 += __shfl_xor_sync(0xffffffffu, pl0, 2);
            pr0 += __shfl_xor_sync(0xffffffffu, pr0, 1); pr0 += __shfl_xor_sync(0xffffffffu, pr0, 2);
            pl1 += __shfl_xor_sync(0xffffffffu, pl1, 1); pl1 += __shfl_xor_sync(0xffffffffu, pl1, 2);
            pr1 += __shfl_xor_sync(0xffffffffu, pr1, 1); pr1 += __shfl_xor_sync(0xffffffffu, pr1, 2);
            if (t4 == 0) {
                int h = wn*4 + hh;
                if (r0 < NN) {
                    g_el[(m*NN + r0)*NH + h] = pl0;
                    g_er[(m*NN + r0)*NH + h] = pr0;
                }
                if (r0 + 8 < NN) {
                    g_el[(m*NN + r0 + 8)*NH + h] = pl1;
                    g_er[(m*NN + r0 + 8)*NH + h] = pr1;
                }
            }
        }
    }
}

// ---- SA GEMM tf32 + fused tanh epilogue ----
__global__ __launch_bounds__(256, 2) void k_sa_mma(const float* __restrict__ B1,
                                                   const float* __restrict__ W2) {
    __shared__ __align__(16) float sA[128*FSTR], sB[128*FSTR];
    __shared__ float s_b1[128], s_w2[128];
    int tid = threadIdx.x, w = tid >> 5, lane = tid & 31;
    int g = lane >> 2, t4 = lane & 3;
    int row0 = blockIdx.x * 128;
    if (tid < 128) { s_b1[tid] = B1[tid]; s_w2[tid] = W2[tid]; }
    uint32_t aA = smem_u32(sA), aB = smem_u32(sB);
    float acc[16][4];
#pragma unroll
    for (int j = 0; j < 16; j++)
#pragma unroll
        for (int i = 0; i < 4; i++) acc[j][i] = 0.f;

    for (int kc = 0; kc < 4; kc++) {
        int k0 = kc * 32;
#pragma unroll
        for (int i = 0; i < 4; i++) {
            int p = i * 256 + tid;
            int r = p >> 3, q = p & 7;
            int row = row0 + r;
            const float* src = g_z + (size_t)(row < SAROWS ? row : 0) * HDIM + k0 + q * 4;
            cp_async16z(aA + (uint32_t)(r*FSTR + q*4)*4, src, row < SAROWS ? 16 : 0);
            cp_async16(aB + (uint32_t)(r*FSTR + q*4)*4, g_w1t + (size_t)r * HDIM + k0 + q * 4);
        }
        CP_COMMIT();
        CP_WAIT0();
        __syncthreads();
#pragma unroll
        for (int ks = 0; ks < 4; ks++) {
            int kb = ks * 8;
            int ar_ = w*16 + g;
            uint32_t af[4];
            af[0] = tf32r_u(sA[ar_*FSTR + kb + t4]);
            af[1] = tf32r_u(sA[(ar_+8)*FSTR + kb + t4]);
            af[2] = tf32r_u(sA[ar_*FSTR + kb + t4 + 4]);
            af[3] = tf32r_u(sA[(ar_+8)*FSTR + kb + t4 + 4]);
#pragma unroll
            for (int jp = 0; jp < 16; jp++) {
                int bn = jp*8 + g;
                uint32_t b0 = __float_as_uint(sB[bn*FSTR + kb + t4]);
                uint32_t b1 = __float_as_uint(sB[bn*FSTR + kb + t4 + 4]);
                mma_tf32(acc[jp], af, b0, b1);
            }
        }
        __syncthreads();
    }
    float s0 = 0.f, s1 = 0.f;
#pragma unroll
    for (int j = 0; j < 16; j++) {
        int col = j * 8 + t4 * 2;
        float b0 = s_b1[col], b1v = s_b1[col + 1];
        float w0 = s_w2[col], w1v = s_w2[col + 1];
        s0 += tanhf(acc[j][0] + b0) * w0 + tanhf(acc[j][1] + b1v) * w1v;
        s1 += tanhf(acc[j][2] + b0) * w0 + tanhf(acc[j][3] + b1v) * w1v;
    }
    s0 += __shfl_xor_sync(0xffffffffu, s0, 1); s0 += __shfl_xor_sync(0xffffffffu, s0, 2);
    s1 += __shfl_xor_sync(0xffffffffu, s1, 1); s1 += __shfl_xor_sync(0xffffffffu, s1, 2);
    if (t4 == 0) {
        int r0 = row0 + w * 16 + g;
        if (r0 < SAROWS)     g_w[r0]     = s0;
        if (r0 + 8 < SAROWS) g_w[r0 + 8] = s1;
    }
}

// ---- CSR build: scalar 1 edge/thread ----
__global__ void k_hist(const int* __restrict__ edges) {
    int idx = blockIdx.x * blockDim.x + threadIdx.x;
    if (idx >= MM*EE) return;
    int m = idx / EE, e = idx - m*EE;
    atomicAdd(&g_deg[m*NN + edges[(size_t)m*2*EE + EE + e]], 1);
}

__global__ void k_scan() {
    __shared__ int sh[1024];
    int m = blockIdx.x, t = threadIdx.x;
    const int CH = (NN + 1023) / 1024;
    int base = t * CH, sum = 0;
    for (int i = 0; i < CH; i++) { int idx = base+i; if (idx < NN) sum += g_deg[m*NN+idx]; }
    sh[t] = sum; __syncthreads();
    for (int d = 1; d < 1024; d <<= 1) {
        int v = (t >= d) ? sh[t-d] : 0; __syncthreads();
        sh[t] += v; __syncthreads();
    }
    int run = sh[t] - sum;
    for (int i = 0; i < CH; i++) {
        int idx = base+i;
        if (idx < NN) { g_off[m*(NN+1)+idx] = run; g_cur[m*NN+idx] = run; run += g_deg[m*NN+idx]; }
    }
    if (t == 1023) g_off[m*(NN+1)+NN] = sh[1023];
}

__global__ void k_scatter(const int* __restrict__ edges) {
    int idx = blockIdx.x * blockDim.x + threadIdx.x;
    if (idx >= MM*EE) return;
    int m = idx / EE, e = idx - m*EE;
    int src = edges[(size_t)m*2*EE + e];
    int dst = edges[(size_t)m*2*EE + EE + e];
    g_srt[(size_t)m*EE + atomicAdd(&g_cur[m*NN + dst], 1)] = src;
}

// ---- GAT aggregation: warp/dst, bf16 gather, unroll-8 (R11/R13 best) ----
__global__ __launch_bounds__(256) void k_agg() {
    int lane = threadIdx.x & 31;
    int wid  = (blockIdx.x * blockDim.x + threadIdx.x) >> 5;
    int m    = blockIdx.y;
    if (wid >= NN) return;
    int n = wid, h = lane >> 2;
    int beg = g_off[m*(NN+1)+n], end = g_off[m*(NN+1)+n+1];
    float ern = g_er[(m*NN+n)*NH + h];
    const __nv_bfloat16* featm = g_feat16 + (size_t)m*HDIM*NN;
    const float* elm = g_el + m*NN*NH;
    const int*   srcs = g_srt + (size_t)m*EE;
    float den = 0.f, ax = 0.f, ay = 0.f, az = 0.f, aw = 0.f;
    float dn2 = 0.f, bx = 0.f, by = 0.f, bz = 0.f, bw = 0.f;
    int i = beg;
    for (; i + 8 <= end; i += 8) {
        int s[8]; float e[8]; uint2 f[8];
#pragma unroll
        for (int j = 0; j < 8; j++) s[j] = __ldg(srcs + i + j);
#pragma unroll
        for (int j = 0; j < 8; j++) e[j] = __ldg(elm + s[j]*NH + h);
#pragma unroll
        for (int j = 0; j < 8; j++) f[j] = *(const uint2*)(featm + (size_t)s[j]*HDIM + lane*4);
#pragma unroll
        for (int j = 0; j < 8; j++) {
            float ev = e[j] + ern;
            ev = (ev > 0.f) ? ev : 0.2f*ev;
            float x = __expf(ev);
            float2 u0 = __bfloat1622float2(*(__nv_bfloat162*)&f[j].x);
            float2 u1 = __bfloat1622float2(*(__nv_bfloat162*)&f[j].y);
            if (j & 1) { dn2 += x; bx += x*u0.x; by += x*u0.y; bz += x*u1.x; bw += x*u1.y; }
            else       { den += x; ax += x*u0.x; ay += x*u0.y; az += x*u1.x; aw += x*u1.y; }
        }
    }
    for (; i + 2 <= end; i += 2) {
        int s0 = __ldg(srcs + i), s1 = __ldg(srcs + i + 1);
        float e0 = __ldg(elm + s0*NH + h) + ern;
        float e1 = __ldg(elm + s1*NH + h) + ern;
        uint2 f0 = *(const uint2*)(featm + (size_t)s0*HDIM + lane*4);
        uint2 f1 = *(const uint2*)(featm + (size_t)s1*HDIM + lane*4);
        e0 = (e0 > 0.f) ? e0 : 0.2f*e0;
        e1 = (e1 > 0.f) ? e1 : 0.2f*e1;
        float x0 = __expf(e0), x1 = __expf(e1);
        den += x0; dn2 += x1;
        float2 u0 = __bfloat1622float2(*(__nv_bfloat162*)&f0.x);
        float2 u1 = __bfloat1622float2(*(__nv_bfloat162*)&f0.y);
        float2 v0 = __bfloat1622float2(*(__nv_bfloat162*)&f1.x);
        float2 v1 = __bfloat1622float2(*(__nv_bfloat162*)&f1.y);
        ax += x0*u0.x; ay += x0*u0.y; az += x0*u1.x; aw += x0*u1.y;
        bx += x1*v0.x; by += x1*v0.y; bz += x1*v1.x; bw += x1*v1.y;
    }
    if (i < end) {
        int s0 = __ldg(srcs + i);
        float e0 = __ldg(elm + s0*NH + h) + ern;
        uint2 f0 = *(const uint2*)(featm + (size_t)s0*HDIM + lane*4);
        e0 = (e0 > 0.f) ? e0 : 0.2f*e0;
        float x0 = __expf(e0);
        den += x0;
        float2 u0 = __bfloat1622float2(*(__nv_bfloat162*)&f0.x);
        float2 u1 = __bfloat1622float2(*(__nv_bfloat162*)&f0.y);
        ax += x0*u0.x; ay += x0*u0.y; az += x0*u1.x; aw += x0*u1.y;
    }
    den += dn2; ax += bx; ay += by; az += bz; aw += bw;
    float inv = (end > beg) ? 1.f/den : 0.f;
    float4 o; float v;
    v = ax*inv; o.x = (v > 0.f) ? v : expm1f(v);
    v = ay*inv; o.y = (v > 0.f) ? v : expm1f(v);
    v = az*inv; o.z = (v > 0.f) ? v : expm1f(v);
    v = aw*inv; o.w = (v > 0.f) ? v : expm1f(v);
    *(float4*)(g_z + (size_t)(n*MM + m)*HDIM + lane*4) = o;
}

// ---- tail: s = exp(w); fus += s*z; den += s; last block does the head ----
__global__ __launch_bounds__(384) void k_tail(const float* __restrict__ PW,
                                              const float* __restrict__ PB,
                                              float* __restrict__ out) {
    int t = threadIdx.x, ms = t >> 7;
    float acc = 0.f, dloc = 0.f;
    for (int n = blockIdx.x; n < NN; n += gridDim.x) {
        float s = __expf(g_w[n*3 + ms]);
        acc += s * g_z[(size_t)n*ZROW + t];
        dloc += s;
    }
    atomicAdd(&g_fus[t], acc);
    if ((t & 127) == 0) atomicAdd(&g_den[ms], dloc);
    // last-block final head
    __threadfence();
    __syncthreads();
    __shared__ int is_last;
    if (t == 0) is_last = (atomicAdd(&g_ctr, 1) == TAIL_GRID - 1);
    __syncthreads();
    if (is_last && t < MM*OUTC) {
        int m = t / OUTC, o = t - m*OUTC;
        float a = 0.f;
#pragma unroll 8
        for (int c = 0; c < HDIM; c++) a += g_fus[m*HDIM + c] * __ldg(PW + c*OUTC + o);
        out[t] = a / g_den[m] + __ldg(PB + o);
    }
}

extern "C" void kernel_launch(void* const* d_in, const int* in_sizes, int n_in,
                              void* d_out, int out_size) {
    const float* h      = (const float*)d_in[0];
    const int*   edges  = (const int*)d_in[1];
    const float* fc_w   = (const float*)d_in[2];
    const float* attn_l = (const float*)d_in[3];
    const float* attn_r = (const float*)d_in[4];
    const float* sa_w1  = (const float*)d_in[5];
    const float* sa_b1  = (const float*)d_in[6];
    const float* sa_w2  = (const float*)d_in[7];
    const float* pred_w = (const float*)d_in[8];
    const float* pred_b = (const float*)d_in[9];
    float* out = (float*)d_out;

    static int inited = 0;
    static cudaStream_t s2;
    static cudaEvent_t ev_fork, ev_join;
    if (!inited) {
        cudaFuncSetAttribute(k_feat_mma, cudaFuncAttributeMaxDynamicSharedMemorySize, FEAT_DYN);
        cudaStreamCreateWithFlags(&s2, cudaStreamNonBlocking);
        cudaEventCreateWithFlags(&ev_fork, cudaEventDisableTiming);
        cudaEventCreateWithFlags(&ev_join, cudaEventDisableTiming);
        inited = 1;
    }

    cudaEventRecord(ev_fork, 0);
    cudaStreamWaitEvent(s2, ev_fork, 0);
    k_init<<<(MM*NN + 255)/256, 256, 0, s2>>>();
    k_hist<<<(MM*EE + 255)/256, 256, 0, s2>>>(edges);
    k_scan<<<MM, 1024, 0, s2>>>();
    k_scatter<<<(MM*EE + 255)/256, 256, 0, s2>>>(edges);
    cudaEventRecord(ev_join, s2);

    k_prep<<<(MM*HDIM*INSZ + SAH*HDIM + MM*HDIM + MM + 1 + 255)/256, 256>>>(fc_w, sa_w1);
    k_feat_mma<<<dim3((NN + 127)/128, MM), 256, FEAT_DYN>>>(h, attn_l, attn_r);

    cudaStreamWaitEvent(0, ev_join, 0);
    k_agg<<<dim3((NN + 7)/8, MM), 256>>>();
    k_sa_mma<<<(SAROWS + 127)/128, 256>>>(sa_b1, sa_w2);
    k_tail<<<TAIL_GRID, 384>>>(pred_w, pred_b, out);
}